// round 6
// baseline (speedup 1.0000x reference)
#include <cuda_runtime.h>
#include <math.h>

// RRoIAlign:
//   K1: NCHW (8,32,160,160) -> NHWC scratch (8,160,160,32). Tile [x][c] stride 33:
//       scalar coalesced LDG + conflict-free STS; conflict-free scalar LDS +
//       coalesced STG.128.
//   K2: grid (1024 rois, 4 row-pairs) x 512 threads. Geometry for 128 bins in smem;
//       coalesced float4 tap gathers (MLP=8); staging smem stride 65 (conflict-free
//       STS); epilogue scalar conflict-free LDS + coalesced STG.32.

namespace {

constexpr int PH = 8;
constexpr int PW = 64;
constexpr int CC = 32;
constexpr int HH = 160;
constexpr int WW = 160;
constexpr int BB = 8;
constexpr float SCALE = 0.25f;

constexpr int IMG   = HH * WW * CC;          // 819200 floats per image
constexpr int ROWF  = WW * CC;               // 5120 floats per pixel-row
constexpr int GUARD = 524288;                // 2MB zero guard each side

__device__ float g_nhwc[GUARD + (size_t)BB * IMG + GUARD];

// ---------------- K1: NCHW -> NHWC transpose ----------------
__global__ __launch_bounds__(256) void transpose_kernel(const float* __restrict__ feat)
{
    __shared__ float tile[WW * 33];          // [x][c], odd stride 33
    const int b = blockIdx.x / HH;
    const int y = blockIdx.x - b * HH;

    // phase 1: scalar LDG (warp = 32 consecutive x, one line) + STS bank x+c (CF)
    const float* src = feat + (size_t)b * IMG + (size_t)y * WW;
#pragma unroll
    for (int i = threadIdx.x; i < WW * CC; i += 256) {       // 20 iters, no warp straddle (160%32==0)
        const int c = i / WW;
        const int x = i - c * WW;
        tile[x * 33 + c] = __ldg(src + (size_t)c * (HH * WW) + x);
    }
    __syncthreads();

    // phase 2: 4 scalar LDS, bank = x + 4cg + j spans all 32 (CF) + STG.128 coalesced
    float* dst = g_nhwc + GUARD + (size_t)b * IMG + (size_t)y * ROWF;
#pragma unroll
    for (int g = threadIdx.x; g < (WW * CC) / 4; g += 256) { // 5 iters
        const int x  = g >> 3;
        const int cg = g & 7;
        const float* tp = &tile[x * 33 + 4 * cg];
        float4 v;
        v.x = tp[0];
        v.y = tp[1];
        v.z = tp[2];
        v.w = tp[3];
        *reinterpret_cast<float4*>(dst + (size_t)x * CC + 4 * cg) = v;
    }
}

// ---------------- K2: gather + blend, 2 rows per block ----------------
__global__ __launch_bounds__(512) void rroi_gather_kernel(
    const float* __restrict__ rois,
    float* __restrict__ out)
{
    __shared__ int    s_base[2 * PW];         // slot = row_local*64 + pw
    __shared__ float4 s_wv[2 * PW];
    __shared__ float  s_r[2][CC * 65];        // staging, odd stride (CF STS)

    const int n   = blockIdx.x;
    const int tid = threadIdx.x;

    if (tid < 2 * PW) {
        const float2* rp = reinterpret_cast<const float2*>(rois + (size_t)n * 6);
        const float2 ra = __ldg(rp + 0);   // batch_idx, cx
        const float2 rb = __ldg(rp + 1);   // cy, h
        const float2 rc = __ldg(rp + 2);   // w, ang

        const int   bidx = (int)ra.x;
        const float cx = ra.y, cy = rb.x, hh = rb.y, ww = rc.x, ang = rc.y;

        const float theta = ang * 0.017453292519943295f;
        float sa, ca;
        sincosf(theta, &sa, &ca);

        const float Sx = ww * SCALE / (float)PW;
        const float Sy = hh * SCALE / (float)PH;
        const float dxc = -(float)PW * 0.5f;
        const float dyc = -(float)PH * 0.5f;
        const float Dx = cx * SCALE;
        const float Dy = cy * SCALE;

        const float M00 = ca * Sx;
        const float M01 = sa * Sy;
        const float M02 = M00 * dxc + M01 * dyc + Dx;
        const float M10 = -sa * Sx;
        const float M11 = ca * Sy;
        const float M12 = M10 * dxc + M11 * dyc + Dy;

        const float pw  = (float)(tid & (PW - 1));
        const float ph  = (float)(blockIdx.y * 2 + (tid >> 6));
        const float pw1 = pw + 1.0f;
        const float ph1 = ph + 1.0f;

        const float X0 = M00 * pw  + M01 * ph  + M02;
        const float X1 = M00 * pw  + M01 * ph1 + M02;
        const float X2 = M00 * pw1 + M01 * ph  + M02;
        const float X3 = M00 * pw1 + M01 * ph1 + M02;
        const float Y0 = M10 * pw  + M11 * ph  + M12;
        const float Y1 = M10 * pw  + M11 * ph1 + M12;
        const float Y2 = M10 * pw1 + M11 * ph  + M12;
        const float Y3 = M10 * pw1 + M11 * ph1 + M12;

        const float xmn = fminf(fminf(X0, X1), fminf(X2, X3));
        const float xmx = fmaxf(fmaxf(X0, X1), fmaxf(X2, X3));
        const float ymn = fminf(fminf(Y0, Y1), fminf(Y2, Y3));
        const float ymx = fmaxf(fmaxf(Y0, Y1), fmaxf(Y2, Y3));

        const float left   = fmaxf(floorf(xmn + 0.5f), 0.0f);
        const float right  = fminf(floorf(xmx + 0.5f), (float)(WW - 1));
        const float top    = fmaxf(floorf(ymn + 0.5f), 0.0f);
        const float bottom = fminf(floorf(ymx + 0.5f), (float)(HH - 1));

        const float bcx = (left + right) * 0.5f;
        const float bcy = (top + bottom) * 0.5f;

        const float bl = floorf(bcx);
        const float br = ceilf(bcx);
        const float bt = floorf(bcy);
        const float bb = ceilf(bcy);
        const float rx = bcx - bl;
        const float ry = bcy - bt;

        const bool vl = (bl > -1.0f) && (bl < (float)WW);
        const bool vr = (br > -1.0f) && (br < (float)WW);
        const bool vt = (bt > -1.0f) && (bt < (float)HH);
        const bool vb = (bb > -1.0f) && (bb < (float)HH);

        // nonzero weight implies ceil==floor+1 on that axis, so the fixed 2x2
        // patch at (yt..yt+1, xl..xl+1) is exact; zero-weight taps may touch
        // the zeroed guard band harmlessly.
        float wlt = (1.0f - rx) * (1.0f - ry);
        float wrt = rx * (1.0f - ry);
        float wlb = (1.0f - rx) * ry;
        float wrb = rx * ry;
        if (!(vt && vl)) wlt = 0.0f;
        if (!(vt && vr)) wrt = 0.0f;
        if (!(vb && vl)) wlb = 0.0f;
        if (!(vb && vr)) wrb = 0.0f;

        const int xl = (int)bl;
        const int yt = (int)bt;

        s_base[tid] = bidx * IMG + (yt * WW + xl) * CC;
        s_wv[tid]   = make_float4(wlt, wrt, wlb, wrb);
    }
    __syncthreads();

    const int bin = tid >> 3;            // 0..63
    const int cg  = tid & 7;             // 4-channel group
    const float* g = g_nhwc + GUARD;

#pragma unroll
    for (int rl = 0; rl < 2; rl++) {
        const int slot  = rl * PW + bin;
        const int base  = s_base[slot] + cg * 4;
        const float4 w  = s_wv[slot];

        const float4 t00 = *reinterpret_cast<const float4*>(g + base);
        const float4 t01 = *reinterpret_cast<const float4*>(g + base + CC);
        const float4 t10 = *reinterpret_cast<const float4*>(g + base + ROWF);
        const float4 t11 = *reinterpret_cast<const float4*>(g + base + ROWF + CC);

        float4 v;
        v.x = w.x * t00.x + w.y * t01.x + w.z * t10.x + w.w * t11.x;
        v.y = w.x * t00.y + w.y * t01.y + w.z * t10.y + w.w * t11.y;
        v.z = w.x * t00.z + w.y * t01.z + w.z * t10.z + w.w * t11.z;
        v.w = w.x * t00.w + w.y * t01.w + w.z * t10.w + w.w * t11.w;

        const int c0 = cg * 4;
        s_r[rl][(c0 + 0) * 65 + bin] = v.x;   // banks 4cg+j+bin: conflict-free
        s_r[rl][(c0 + 1) * 65 + bin] = v.y;
        s_r[rl][(c0 + 2) * 65 + bin] = v.z;
        s_r[rl][(c0 + 3) * 65 + bin] = v.w;
    }
    __syncthreads();

    // epilogue: per warp x spans 32 consecutive, c fixed -> LDS bank c+x (CF),
    // STG.32 coalesced (128B per warp-instr)
    const int r0 = blockIdx.y * 2;
    float* ob = out + (size_t)n * (CC * PH * PW);

#pragma unroll
    for (int rl = 0; rl < 2; rl++) {
#pragma unroll
        for (int j = 0; j < 4; j++) {
            const int i = tid + 512 * j;      // 0..2047
            const int c = i >> 6;
            const int x = i & 63;
            ob[(size_t)c * (PH * PW) + (r0 + rl) * PW + x] = s_r[rl][c * 65 + x];
        }
    }
}

}  // namespace

extern "C" void kernel_launch(void* const* d_in, const int* in_sizes, int n_in,
                              void* d_out, int out_size) {
    const float* features = (const float*)d_in[0];
    const float* rois     = (const float*)d_in[1];
    float* out            = (float*)d_out;

    const int N = in_sizes[1] / 6;  // 1024

    transpose_kernel<<<BB * HH, 256>>>(features);
    dim3 grid(N, PH / 2);
    rroi_gather_kernel<<<grid, 512>>>(rois, out);
}

// round 7
// speedup vs baseline: 1.0539x; 1.0539x over previous
#include <cuda_runtime.h>
#include <math.h>

// RRoIAlign:
//   K1: NCHW (8,32,160,160) -> NHWC scratch (8,160,160,32), vectorized (R5 version).
//   K2: grid (1024 rois, 4 row-pairs) x 512 threads. Geometry for 128 bins in smem;
//       all 8 tap LDG.128s batched up-front (MLP=8, launch_bounds 512,2);
//       staging smem stride 65 (CF STS); epilogue LDS + coalesced STG.128,
//       output stores streaming (evict-first) to protect L2-resident scratch.

namespace {

constexpr int PH = 8;
constexpr int PW = 64;
constexpr int CC = 32;
constexpr int HH = 160;
constexpr int WW = 160;
constexpr int BB = 8;
constexpr float SCALE = 0.25f;

constexpr int IMG   = HH * WW * CC;          // 819200 floats per image
constexpr int ROWF  = WW * CC;               // 5120 floats per pixel-row
constexpr int GUARD = 524288;                // 2MB zero guard each side

__device__ float g_nhwc[GUARD + (size_t)BB * IMG + GUARD];

__device__ __forceinline__ void stcs_f4(float* p, float4 v) {
    asm volatile("st.global.cs.v4.f32 [%0], {%1, %2, %3, %4};"
                 :: "l"(p), "f"(v.x), "f"(v.y), "f"(v.z), "f"(v.w) : "memory");
}

// ---------------- K1: NCHW -> NHWC transpose (R5 version) ----------------
__global__ __launch_bounds__(256) void transpose_kernel(const float* __restrict__ feat)
{
    __shared__ float tile[CC * 164];
    const int b = blockIdx.x / HH;
    const int y = blockIdx.x - b * HH;

    const float* src = feat + (size_t)b * IMG + (size_t)y * WW;
#pragma unroll
    for (int f = threadIdx.x; f < CC * (WW / 4); f += 256) {
        const int c  = f / (WW / 4);
        const int x4 = f - c * (WW / 4);
        const float4 v = __ldg(reinterpret_cast<const float4*>(src + (size_t)c * (HH * WW) + x4 * 4));
        *reinterpret_cast<float4*>(&tile[c * 164 + x4 * 4]) = v;
    }
    __syncthreads();

    float* dst = g_nhwc + GUARD + (size_t)b * IMG + (size_t)y * ROWF;
#pragma unroll
    for (int g = threadIdx.x; g < (WW * CC) / 4; g += 256) {
        const int x  = g >> 3;
        const int cg = g & 7;
        float4 v;
        v.x = tile[(4 * cg + 0) * 164 + x];
        v.y = tile[(4 * cg + 1) * 164 + x];
        v.z = tile[(4 * cg + 2) * 164 + x];
        v.w = tile[(4 * cg + 3) * 164 + x];
        *reinterpret_cast<float4*>(dst + (size_t)x * CC + 4 * cg) = v;
    }
}

// ---------------- K2: gather + blend, 2 rows per block ----------------
__global__ __launch_bounds__(512, 2) void rroi_gather_kernel(
    const float* __restrict__ rois,
    float* __restrict__ out)
{
    __shared__ int    s_base[2 * PW];         // slot = row_local*64 + pw
    __shared__ float4 s_wv[2 * PW];
    __shared__ float  s_r[2][CC * 65];        // staging, odd stride (CF STS)

    const int n   = blockIdx.x;
    const int tid = threadIdx.x;

    if (tid < 2 * PW) {
        const float2* rp = reinterpret_cast<const float2*>(rois + (size_t)n * 6);
        const float2 ra = __ldg(rp + 0);   // batch_idx, cx
        const float2 rb = __ldg(rp + 1);   // cy, h
        const float2 rc = __ldg(rp + 2);   // w, ang

        const int   bidx = (int)ra.x;
        const float cx = ra.y, cy = rb.x, hh = rb.y, ww = rc.x, ang = rc.y;

        const float theta = ang * 0.017453292519943295f;
        float sa, ca;
        sincosf(theta, &sa, &ca);

        const float Sx = ww * SCALE / (float)PW;
        const float Sy = hh * SCALE / (float)PH;
        const float dxc = -(float)PW * 0.5f;
        const float dyc = -(float)PH * 0.5f;
        const float Dx = cx * SCALE;
        const float Dy = cy * SCALE;

        const float M00 = ca * Sx;
        const float M01 = sa * Sy;
        const float M02 = M00 * dxc + M01 * dyc + Dx;
        const float M10 = -sa * Sx;
        const float M11 = ca * Sy;
        const float M12 = M10 * dxc + M11 * dyc + Dy;

        const float pw  = (float)(tid & (PW - 1));
        const float ph  = (float)(blockIdx.y * 2 + (tid >> 6));
        const float pw1 = pw + 1.0f;
        const float ph1 = ph + 1.0f;

        const float X0 = M00 * pw  + M01 * ph  + M02;
        const float X1 = M00 * pw  + M01 * ph1 + M02;
        const float X2 = M00 * pw1 + M01 * ph  + M02;
        const float X3 = M00 * pw1 + M01 * ph1 + M02;
        const float Y0 = M10 * pw  + M11 * ph  + M12;
        const float Y1 = M10 * pw  + M11 * ph1 + M12;
        const float Y2 = M10 * pw1 + M11 * ph  + M12;
        const float Y3 = M10 * pw1 + M11 * ph1 + M12;

        const float xmn = fminf(fminf(X0, X1), fminf(X2, X3));
        const float xmx = fmaxf(fmaxf(X0, X1), fmaxf(X2, X3));
        const float ymn = fminf(fminf(Y0, Y1), fminf(Y2, Y3));
        const float ymx = fmaxf(fmaxf(Y0, Y1), fmaxf(Y2, Y3));

        const float left   = fmaxf(floorf(xmn + 0.5f), 0.0f);
        const float right  = fminf(floorf(xmx + 0.5f), (float)(WW - 1));
        const float top    = fmaxf(floorf(ymn + 0.5f), 0.0f);
        const float bottom = fminf(floorf(ymx + 0.5f), (float)(HH - 1));

        const float bcx = (left + right) * 0.5f;
        const float bcy = (top + bottom) * 0.5f;

        const float bl = floorf(bcx);
        const float br = ceilf(bcx);
        const float bt = floorf(bcy);
        const float bb = ceilf(bcy);
        const float rx = bcx - bl;
        const float ry = bcy - bt;

        const bool vl = (bl > -1.0f) && (bl < (float)WW);
        const bool vr = (br > -1.0f) && (br < (float)WW);
        const bool vt = (bt > -1.0f) && (bt < (float)HH);
        const bool vb = (bb > -1.0f) && (bb < (float)HH);

        // nonzero weight implies ceil==floor+1 on that axis, so the fixed 2x2
        // patch at (yt..yt+1, xl..xl+1) is exact; zero-weight taps may touch
        // the zeroed guard band harmlessly.
        float wlt = (1.0f - rx) * (1.0f - ry);
        float wrt = rx * (1.0f - ry);
        float wlb = (1.0f - rx) * ry;
        float wrb = rx * ry;
        if (!(vt && vl)) wlt = 0.0f;
        if (!(vt && vr)) wrt = 0.0f;
        if (!(vb && vl)) wlb = 0.0f;
        if (!(vb && vr)) wrb = 0.0f;

        const int xl = (int)bl;
        const int yt = (int)bt;

        s_base[tid] = bidx * IMG + (yt * WW + xl) * CC;
        s_wv[tid]   = make_float4(wlt, wrt, wlb, wrb);
    }
    __syncthreads();

    const int bin = tid >> 3;            // 0..63
    const int cg  = tid & 7;             // 4-channel group
    const float* g = g_nhwc + GUARD;

    // batch all 8 tap loads (both rows) before any blend -> MLP = 8
    const int base0 = s_base[bin] + cg * 4;
    const int base1 = s_base[PW + bin] + cg * 4;

    float4 t[2][4];
    t[0][0] = *reinterpret_cast<const float4*>(g + base0);
    t[0][1] = *reinterpret_cast<const float4*>(g + base0 + CC);
    t[0][2] = *reinterpret_cast<const float4*>(g + base0 + ROWF);
    t[0][3] = *reinterpret_cast<const float4*>(g + base0 + ROWF + CC);
    t[1][0] = *reinterpret_cast<const float4*>(g + base1);
    t[1][1] = *reinterpret_cast<const float4*>(g + base1 + CC);
    t[1][2] = *reinterpret_cast<const float4*>(g + base1 + ROWF);
    t[1][3] = *reinterpret_cast<const float4*>(g + base1 + ROWF + CC);

#pragma unroll
    for (int rl = 0; rl < 2; rl++) {
        const float4 w = s_wv[rl * PW + bin];
        float4 v;
        v.x = w.x * t[rl][0].x + w.y * t[rl][1].x + w.z * t[rl][2].x + w.w * t[rl][3].x;
        v.y = w.x * t[rl][0].y + w.y * t[rl][1].y + w.z * t[rl][2].y + w.w * t[rl][3].y;
        v.z = w.x * t[rl][0].z + w.y * t[rl][1].z + w.z * t[rl][2].z + w.w * t[rl][3].z;
        v.w = w.x * t[rl][0].w + w.y * t[rl][1].w + w.z * t[rl][2].w + w.w * t[rl][3].w;

        const int c0 = cg * 4;
        s_r[rl][(c0 + 0) * 65 + bin] = v.x;   // banks 4cg+j+bin: conflict-free
        s_r[rl][(c0 + 1) * 65 + bin] = v.y;
        s_r[rl][(c0 + 2) * 65 + bin] = v.z;
        s_r[rl][(c0 + 3) * 65 + bin] = v.w;
    }
    __syncthreads();

    // epilogue: 4x LDS.32 (<=2-way conflict) + coalesced streaming STG.128 per row
    const int c  = tid >> 4;             // 0..31
    const int x4 = tid & 15;             // 0..15
    const int r0 = blockIdx.y * 2;
    float* ob = out + (size_t)n * (CC * PH * PW) + (size_t)c * (PH * PW);

#pragma unroll
    for (int rl = 0; rl < 2; rl++) {
        const float* sr = &s_r[rl][c * 65 + x4 * 4];
        float4 v;
        v.x = sr[0];
        v.y = sr[1];
        v.z = sr[2];
        v.w = sr[3];
        stcs_f4(ob + (r0 + rl) * PW + x4 * 4, v);
    }
}

}  // namespace

extern "C" void kernel_launch(void* const* d_in, const int* in_sizes, int n_in,
                              void* d_out, int out_size) {
    const float* features = (const float*)d_in[0];
    const float* rois     = (const float*)d_in[1];
    float* out            = (float*)d_out;

    const int N = in_sizes[1] / 6;  // 1024

    transpose_kernel<<<BB * HH, 256>>>(features);
    dim3 grid(N, PH / 2);
    rroi_gather_kernel<<<grid, 512>>>(rois, out);
}